// round 14
// baseline (speedup 1.0000x reference)
#include <cuda_runtime.h>
#include <cuda_fp16.h>
#include <cstdint>

// DilateAttention: B=4, d=384 (12 heads x 32), H=W=64, 3x3 kernel, dilation 2, zero pad 2.
// q,k,v: [B, 384, 64, 64] f32. out: [B, 64, 64, 384] f32.
// fp16 K/V smem tiles, TH=8 (12-row halo planes), 512 threads, 2 CTAs/SM (50% occ).
// Thread = (pixel pair (w,w+1)) x (16-channel half); one LDS.32 = half2 = both
// pixels; lanes i/i+16 combine QK partials via packed shfl_xor(16).

#define NH  12
#define HD  32
#define HH  64
#define WW  64
#define TH  8
#define RR  12                      // TH + 4 halo rows
#define CCH 68                      // halves per row (64 + 2 pad each side)
#define PSH (RR * CCH)              // 816 halves per channel plane
#define HI_OFF (16 * PSH + 32)      // ch>=16 base (+16 words -> disjoint bank halves)
#define TILE_HALVES (32 * PSH + 32) // 26144 halves = 52288 B
#define SCALE 0.17677669529663689f

__device__ __forceinline__ uint64_t pack2(float lo, float hi) {
    uint64_t r; asm("mov.b64 %0, {%1, %2};" : "=l"(r) : "f"(lo), "f"(hi)); return r;
}
__device__ __forceinline__ void unpack2(uint64_t v, float& lo, float& hi) {
    asm("mov.b64 {%0, %1}, %2;" : "=f"(lo), "=f"(hi) : "l"(v));
}
__device__ __forceinline__ void ffma2(uint64_t& d, uint64_t a, uint64_t b) {
    asm("fma.rn.f32x2 %0, %1, %2, %0;" : "+l"(d) : "l"(a), "l"(b));
}
__device__ __forceinline__ uint64_t fadd2(uint64_t a, uint64_t b) {
    uint64_t d; asm("add.rn.f32x2 %0, %1, %2;" : "=l"(d) : "l"(a), "l"(b)); return d;
}
__device__ __forceinline__ uint64_t fmul2(uint64_t a, uint64_t b) {
    uint64_t d; asm("mul.rn.f32x2 %0, %1, %2;" : "=l"(d) : "l"(a), "l"(b)); return d;
}
__device__ __forceinline__ uint64_t h2_to_f2(__half2 h) {
    const float2 f = __half22float2(h);
    return pack2(f.x, f.y);
}

// Warp-cooperative fp32->fp16 staging: each of 16 warps stages 24 of the 384
// halo rows (6 groups of 4 rows; per group the warp touches 4x128B lines).
__device__ __forceinline__ void stage_tensor(const float* __restrict__ src,
                                             __half* tile, int wp, int lane,
                                             int h0, size_t base) {
    const int sub   = lane >> 3;    // 0..3  row within group
    const int chunk = lane & 7;     // 0..7  float4 chunk
    #pragma unroll
    for (int p = 0; p < 6; p++) {
        const int R  = wp * 24 + p * 4 + sub;    // global halo row 0..383
        const int c  = R / RR;                   // channel 0..31
        const int sr = R - c * RR;               // halo row 0..11
        const int gh = h0 - 2 + sr;
        const bool inb = (unsigned)gh < HH;
        const int hrow = c * PSH + ((c >= 16) ? 32 : 0) + sr * CCH;
        const float* g = src + base + (size_t)c * (HH * WW) + gh * WW;
        #pragma unroll
        for (int i = 0; i < 2; i++) {
            const int f4 = chunk + 8 * i;        // 0..15
            float4 val = make_float4(0.f, 0.f, 0.f, 0.f);
            if (inb) val = *(const float4*)(g + f4 * 4);
            *(__half2*)(tile + hrow + 2 + f4 * 4)     = __floats2half2_rn(val.x, val.y);
            *(__half2*)(tile + hrow + 2 + f4 * 4 + 2) = __floats2half2_rn(val.z, val.w);
        }
        if (chunk == 0) *(__half2*)(tile + hrow)      = __float2half2_rn(0.f);
        if (chunk == 7) *(__half2*)(tile + hrow + 66) = __float2half2_rn(0.f);
    }
}

__global__ __launch_bounds__(512, 2)
void dilate_attn_kernel(const float* __restrict__ q,
                        const float* __restrict__ k,
                        const float* __restrict__ v,
                        float* __restrict__ out)
{
    extern __shared__ __half tile[];

    const int tid  = threadIdx.x;           // 0..511
    const int lane = tid & 31;
    const int wp   = tid >> 5;              // warp 0..15
    const int pair = wp * 16 + (lane & 15); // 0..255
    const int row  = pair >> 5;             // 0..7  pixel row in tile
    const int w    = (pair & 31) * 2;       // even pixel column
    const int ch0  = lane & 16;             // 0 or 16: channel half base

    const int h0   = blockIdx.x * TH;
    const int bh   = blockIdx.y;            // 0..47
    const int b    = bh / NH;
    const int head = bh - b * NH;
    const size_t base = ((size_t)b * 384 + (size_t)head * HD) * (HH * WW);

    // ---- q: 16 channels x 2 pixels packed (coalesced LDG.64) ----
    const int h = h0 + row;
    uint64_t q2[16];
    {
        const uint64_t* qp =
            (const uint64_t*)(q + base + (size_t)ch0 * (HH * WW) + h * WW + w);
        #pragma unroll
        for (int c = 0; c < 16; c++) q2[c] = __ldg(qp + (size_t)c * 2048);
    }

    // ---- stage k as fp16 ----
    stage_tensor(k, tile, wp, lane, h0, base);
    __syncthreads();                        // bar1: k tile visible

    // ---- QK: packed partial logits over this thread's 16 channels ----
    const int chbase = ch0 ? HI_OFF : 0;
    uint64_t lg2[9];
    #pragma unroll
    for (int kp = 0; kp < 9; kp++) {
        const int di = kp / 3;
        const int dj = kp - di * 3;
        const __half2* kr =
            (const __half2*)(tile + chbase + (row + 2 * di) * CCH + w + 2 * dj);
        uint64_t a = 0;
        #pragma unroll
        for (int c = 0; c < 16; c++)
            ffma2(a, q2[c], h2_to_f2(kr[c * (PSH / 2)]));
        lg2[kp] = a;
    }

    __syncthreads();                        // bar2: all k reads done

    // ---- restage v (LDG latency overlaps shuffle + softmax below) ----
    stage_tensor(v, tile, wp, lane, h0, base);

    // ---- combine halves (packed shuffle) + softmax for both pixels ----
    float l0[9], l1[9];
    #pragma unroll
    for (int kp = 0; kp < 9; kp++) {
        const double part = __longlong_as_double((long long)lg2[kp]);
        const double oth  = __shfl_xor_sync(0xffffffffu, part, 16);
        const uint64_t full = fadd2(lg2[kp], (uint64_t)__double_as_longlong(oth));
        unpack2(full, l0[kp], l1[kp]);
        l0[kp] *= SCALE; l1[kp] *= SCALE;   // OOB neighbor: k==0 -> logit 0 (zero-pad)
    }
    float m0 = l0[0], m1 = l1[0];
    #pragma unroll
    for (int kp = 1; kp < 9; kp++) { m0 = fmaxf(m0, l0[kp]); m1 = fmaxf(m1, l1[kp]); }
    float sum0 = 0.f, sum1 = 0.f;
    uint64_t p2[9];
    #pragma unroll
    for (int kp = 0; kp < 9; kp++) {
        const float e0 = __expf(l0[kp] - m0);
        const float e1 = __expf(l1[kp] - m1);
        sum0 += e0; sum1 += e1;
        p2[kp] = pack2(e0, e1);
    }
    const uint64_t inv2 = pack2(__fdividef(1.f, sum0), __fdividef(1.f, sum1));

    __syncthreads();                        // bar3: v tile visible

    // ---- AV: packed weighted sum over this thread's 16 channels ----
    uint64_t acc2[16];
    #pragma unroll
    for (int c = 0; c < 16; c++) acc2[c] = 0;
    #pragma unroll
    for (int kp = 0; kp < 9; kp++) {
        const int di = kp / 3;
        const int dj = kp - di * 3;
        const __half2* vr =
            (const __half2*)(tile + chbase + (row + 2 * di) * CCH + w + 2 * dj);
        #pragma unroll
        for (int c = 0; c < 16; c++)
            ffma2(acc2[c], p2[kp], h2_to_f2(vr[c * (PSH / 2)]));
    }

    // ---- stores: 2 pixels x 64B contiguous each (8 STG.128 total) ----
    const size_t ob = (((size_t)b * HH + h) * WW + w) * 384
                      + (size_t)head * HD + ch0;
    float4* d0 = (float4*)(out + ob);           // pixel w
    float4* d1 = (float4*)(out + ob + 384);     // pixel w+1
    #pragma unroll
    for (int i = 0; i < 4; i++) {
        float x0, y0, x1, y1, x2, y2, x3, y3;
        unpack2(fmul2(acc2[4 * i + 0], inv2), x0, y0);
        unpack2(fmul2(acc2[4 * i + 1], inv2), x1, y1);
        unpack2(fmul2(acc2[4 * i + 2], inv2), x2, y2);
        unpack2(fmul2(acc2[4 * i + 3], inv2), x3, y3);
        d0[i] = make_float4(x0, x1, x2, x3);
        d1[i] = make_float4(y0, y1, y2, y3);
    }
}

extern "C" void kernel_launch(void* const* d_in, const int* in_sizes, int n_in,
                              void* d_out, int out_size)
{
    const float* q = (const float*)d_in[0];
    const float* k = (const float*)d_in[1];
    const float* v = (const float*)d_in[2];
    float* out = (float*)d_out;

    const int smem_bytes = TILE_HALVES * sizeof(__half);   // 52288
    cudaFuncSetAttribute(dilate_attn_kernel,
                         cudaFuncAttributeMaxDynamicSharedMemorySize, smem_bytes);

    dim3 block(512, 1, 1);
    dim3 grid(HH / TH, 4 * NH, 1);         // (8, 48)
    dilate_attn_kernel<<<grid, block, smem_bytes>>>(q, k, v, out);
}

// round 15
// speedup vs baseline: 1.0292x; 1.0292x over previous
#include <cuda_runtime.h>
#include <cuda_fp16.h>
#include <cstdint>

// DilateAttention: B=4, d=384 (12 heads x 32), H=W=64, 3x3 kernel, dilation 2, zero pad 2.
// q,k,v: [B, 384, 64, 64] f32. out: [B, 64, 64, 384] f32.
// SINGLE-BARRIER kernel: K and V both resident as fp16 smem tiles (2 x 52.3KB,
// TH=8, 512 thr, 2 CTAs/SM). All DRAM latency concentrated in one prologue.
// Thread = (pixel pair (w,w+1)) x (16-channel half); one LDS.32 = half2 = both
// pixels; lanes i/i+16 combine QK partials via packed shfl_xor(16).

#define NH  12
#define HD  32
#define HH  64
#define WW  64
#define TH  8
#define RR  12                      // TH + 4 halo rows
#define CCH 68                      // halves per row (64 + 2 pad each side)
#define PSH (RR * CCH)              // 816 halves per channel plane
#define HI_OFF (16 * PSH + 32)      // ch>=16 base (+16 words -> disjoint bank halves)
#define TILE_HALVES (32 * PSH + 32) // 26144 halves = 52288 B per tensor
#define SCALE 0.17677669529663689f

__device__ __forceinline__ uint64_t pack2(float lo, float hi) {
    uint64_t r; asm("mov.b64 %0, {%1, %2};" : "=l"(r) : "f"(lo), "f"(hi)); return r;
}
__device__ __forceinline__ void unpack2(uint64_t v, float& lo, float& hi) {
    asm("mov.b64 {%0, %1}, %2;" : "=f"(lo), "=f"(hi) : "l"(v));
}
__device__ __forceinline__ void ffma2(uint64_t& d, uint64_t a, uint64_t b) {
    asm("fma.rn.f32x2 %0, %1, %2, %0;" : "+l"(d) : "l"(a), "l"(b));
}
__device__ __forceinline__ uint64_t fadd2(uint64_t a, uint64_t b) {
    uint64_t d; asm("add.rn.f32x2 %0, %1, %2;" : "=l"(d) : "l"(a), "l"(b)); return d;
}
__device__ __forceinline__ uint64_t fmul2(uint64_t a, uint64_t b) {
    uint64_t d; asm("mul.rn.f32x2 %0, %1, %2;" : "=l"(d) : "l"(a), "l"(b)); return d;
}
__device__ __forceinline__ uint64_t h2_to_f2(__half2 h) {
    const float2 f = __half22float2(h);
    return pack2(f.x, f.y);
}

// Warp-cooperative fp32->fp16 staging: each of 16 warps stages 24 of the 384
// halo rows (6 groups of 4 rows; per group the warp touches 4 x 128B lines).
__device__ __forceinline__ void stage_tensor(const float* __restrict__ src,
                                             __half* tile, int wp, int lane,
                                             int h0, size_t base) {
    const int sub   = lane >> 3;    // 0..3  row within group
    const int chunk = lane & 7;     // 0..7  float4 chunk
    #pragma unroll
    for (int p = 0; p < 6; p++) {
        const int R  = wp * 24 + p * 4 + sub;    // global halo row 0..383
        const int c  = R / RR;                   // channel 0..31
        const int sr = R - c * RR;               // halo row 0..11
        const int gh = h0 - 2 + sr;
        const bool inb = (unsigned)gh < HH;
        const int hrow = c * PSH + ((c >= 16) ? 32 : 0) + sr * CCH;
        const float* g = src + base + (size_t)c * (HH * WW) + gh * WW;
        #pragma unroll
        for (int i = 0; i < 2; i++) {
            const int f4 = chunk + 8 * i;        // 0..15
            float4 val = make_float4(0.f, 0.f, 0.f, 0.f);
            if (inb) val = *(const float4*)(g + f4 * 4);
            *(__half2*)(tile + hrow + 2 + f4 * 4)     = __floats2half2_rn(val.x, val.y);
            *(__half2*)(tile + hrow + 2 + f4 * 4 + 2) = __floats2half2_rn(val.z, val.w);
        }
        if (chunk == 0) *(__half2*)(tile + hrow)      = __float2half2_rn(0.f);
        if (chunk == 7) *(__half2*)(tile + hrow + 66) = __float2half2_rn(0.f);
    }
}

__global__ __launch_bounds__(512, 2)
void dilate_attn_kernel(const float* __restrict__ q,
                        const float* __restrict__ k,
                        const float* __restrict__ v,
                        float* __restrict__ out)
{
    extern __shared__ __half smem[];
    __half* kt = smem;                       // k tile
    __half* vt = smem + TILE_HALVES;         // v tile

    const int tid  = threadIdx.x;            // 0..511
    const int lane = tid & 31;
    const int wp   = tid >> 5;               // warp 0..15
    const int pair = wp * 16 + (lane & 15);  // 0..255
    const int row  = pair >> 5;              // 0..7  pixel row in tile
    const int w    = (pair & 31) * 2;        // even pixel column
    const int ch0  = lane & 16;              // 0 or 16: channel half base

    const int h0   = blockIdx.x * TH;
    const int bh   = blockIdx.y;             // 0..47
    const int b    = bh / NH;
    const int head = bh - b * NH;
    const size_t base = ((size_t)b * 384 + (size_t)head * HD) * (HH * WW);

    // ---- q: 16 channels x 2 pixels packed (coalesced LDG.64, issued first) ----
    const int h = h0 + row;
    uint64_t q2[16];
    {
        const uint64_t* qp =
            (const uint64_t*)(q + base + (size_t)ch0 * (HH * WW) + h * WW + w);
        #pragma unroll
        for (int c = 0; c < 16; c++) q2[c] = __ldg(qp + (size_t)c * 2048);
    }

    // ---- stage BOTH tensors as fp16 (one big MLP-rich burst) ----
    stage_tensor(k, kt, wp, lane, h0, base);
    stage_tensor(v, vt, wp, lane, h0, base);

    __syncthreads();                         // THE barrier

    // ---- QK: packed partial logits over this thread's 16 channels ----
    const int chbase = ch0 ? HI_OFF : 0;
    uint64_t lg2[9];
    #pragma unroll
    for (int kp = 0; kp < 9; kp++) {
        const int di = kp / 3;
        const int dj = kp - di * 3;
        const __half2* kr =
            (const __half2*)(kt + chbase + (row + 2 * di) * CCH + w + 2 * dj);
        uint64_t a = 0;
        #pragma unroll
        for (int c = 0; c < 16; c++)
            ffma2(a, q2[c], h2_to_f2(kr[c * (PSH / 2)]));
        lg2[kp] = a;
    }

    // ---- combine halves (packed shuffle) + softmax for both pixels ----
    float l0[9], l1[9];
    #pragma unroll
    for (int kp = 0; kp < 9; kp++) {
        const double part = __longlong_as_double((long long)lg2[kp]);
        const double oth  = __shfl_xor_sync(0xffffffffu, part, 16);
        const uint64_t full = fadd2(lg2[kp], (uint64_t)__double_as_longlong(oth));
        unpack2(full, l0[kp], l1[kp]);
        l0[kp] *= SCALE; l1[kp] *= SCALE;    // OOB neighbor: k==0 -> logit 0 (zero-pad)
    }
    float m0 = l0[0], m1 = l1[0];
    #pragma unroll
    for (int kp = 1; kp < 9; kp++) { m0 = fmaxf(m0, l0[kp]); m1 = fmaxf(m1, l1[kp]); }
    float sum0 = 0.f, sum1 = 0.f;
    uint64_t p2[9];
    #pragma unroll
    for (int kp = 0; kp < 9; kp++) {
        const float e0 = __expf(l0[kp] - m0);
        const float e1 = __expf(l1[kp] - m1);
        sum0 += e0; sum1 += e1;
        p2[kp] = pack2(e0, e1);
    }
    const uint64_t inv2 = pack2(__fdividef(1.f, sum0), __fdividef(1.f, sum1));

    // ---- AV: packed weighted sum over this thread's 16 channels ----
    uint64_t acc2[16];
    #pragma unroll
    for (int c = 0; c < 16; c++) acc2[c] = 0;
    #pragma unroll
    for (int kp = 0; kp < 9; kp++) {
        const int di = kp / 3;
        const int dj = kp - di * 3;
        const __half2* vr =
            (const __half2*)(vt + chbase + (row + 2 * di) * CCH + w + 2 * dj);
        #pragma unroll
        for (int c = 0; c < 16; c++)
            ffma2(acc2[c], p2[kp], h2_to_f2(vr[c * (PSH / 2)]));
    }

    // ---- stores: 2 pixels x 64B contiguous each (8 STG.128 total) ----
    const size_t ob = (((size_t)b * HH + h) * WW + w) * 384
                      + (size_t)head * HD + ch0;
    float4* d0 = (float4*)(out + ob);            // pixel w
    float4* d1 = (float4*)(out + ob + 384);      // pixel w+1
    #pragma unroll
    for (int i = 0; i < 4; i++) {
        float x0, y0, x1, y1, x2, y2, x3, y3;
        unpack2(fmul2(acc2[4 * i + 0], inv2), x0, y0);
        unpack2(fmul2(acc2[4 * i + 1], inv2), x1, y1);
        unpack2(fmul2(acc2[4 * i + 2], inv2), x2, y2);
        unpack2(fmul2(acc2[4 * i + 3], inv2), x3, y3);
        d0[i] = make_float4(x0, x1, x2, x3);
        d1[i] = make_float4(y0, y1, y2, y3);
    }
}

extern "C" void kernel_launch(void* const* d_in, const int* in_sizes, int n_in,
                              void* d_out, int out_size)
{
    const float* q = (const float*)d_in[0];
    const float* k = (const float*)d_in[1];
    const float* v = (const float*)d_in[2];
    float* out = (float*)d_out;

    const int smem_bytes = 2 * TILE_HALVES * sizeof(__half);   // 104576
    cudaFuncSetAttribute(dilate_attn_kernel,
                         cudaFuncAttributeMaxDynamicSharedMemorySize, smem_bytes);

    dim3 block(512, 1, 1);
    dim3 grid(HH / TH, 4 * NH, 1);          // (8, 48)
    dilate_attn_kernel<<<grid, block, smem_bytes>>>(q, k, v, out);
}

// round 16
// speedup vs baseline: 1.1254x; 1.0935x over previous
#include <cuda_runtime.h>
#include <cuda_fp16.h>
#include <cstdint>

// DilateAttention: B=4, d=384 (12 heads x 32), H=W=64, 3x3 kernel, dilation 2, zero pad 2.
// q,k,v: [B, 384, 64, 64] f32. out: [B, 64, 64, 384] f32.
// Single-barrier, both K and V resident as fp16 tiles (2 x 34.9KB), TH=4,
// 256 threads, 3 CTAs/SM (85-reg budget -> no spills, unlike the 512-thr
// 64-reg variants). Thread = (pixel pair (w,w+1)) x (16-channel half);
// one LDS.32 = half2 = both pixels; packed shfl_xor(16) combines halves.

#define NH  12
#define HD  32
#define HH  64
#define WW  64
#define TH  4
#define RR  8                       // TH + 4 halo rows
#define CCH 68                      // halves per row (64 + 2 pad each side)
#define PSH (RR * CCH)              // 544 halves per channel plane
#define HI_OFF (16 * PSH + 32)      // ch>=16 base (+32 halves -> disjoint bank halves)
#define TILE_HALVES (32 * PSH + 32) // 17440 halves = 34880 B per tensor
#define SCALE 0.17677669529663689f

__device__ __forceinline__ uint64_t pack2(float lo, float hi) {
    uint64_t r; asm("mov.b64 %0, {%1, %2};" : "=l"(r) : "f"(lo), "f"(hi)); return r;
}
__device__ __forceinline__ void unpack2(uint64_t v, float& lo, float& hi) {
    asm("mov.b64 {%0, %1}, %2;" : "=f"(lo), "=f"(hi) : "l"(v));
}
__device__ __forceinline__ void ffma2(uint64_t& d, uint64_t a, uint64_t b) {
    asm("fma.rn.f32x2 %0, %1, %2, %0;" : "+l"(d) : "l"(a), "l"(b));
}
__device__ __forceinline__ uint64_t fadd2(uint64_t a, uint64_t b) {
    uint64_t d; asm("add.rn.f32x2 %0, %1, %2;" : "=l"(d) : "l"(a), "l"(b)); return d;
}
__device__ __forceinline__ uint64_t fmul2(uint64_t a, uint64_t b) {
    uint64_t d; asm("mul.rn.f32x2 %0, %1, %2;" : "=l"(d) : "l"(a), "l"(b)); return d;
}
__device__ __forceinline__ uint64_t h2_to_f2(__half2 h) {
    const float2 f = __half22float2(h);
    return pack2(f.x, f.y);
}

// Warp-cooperative fp32->fp16 staging: each of 8 warps stages 32 of the 256
// halo rows (8 groups of 4 rows; per group the warp touches 4 x 128B lines).
__device__ __forceinline__ void stage_tensor(const float* __restrict__ src,
                                             __half* tile, int wp, int lane,
                                             int h0, size_t base) {
    const int sub   = lane >> 3;    // 0..3  row within group
    const int chunk = lane & 7;     // 0..7  float4 chunk
    #pragma unroll
    for (int p = 0; p < 8; p++) {
        const int R  = wp * 32 + p * 4 + sub;    // global halo row 0..255
        const int c  = R >> 3;                   // channel 0..31
        const int sr = R & 7;                    // halo row 0..7
        const int gh = h0 - 2 + sr;
        const bool inb = (unsigned)gh < HH;
        const int hrow = c * PSH + ((c >= 16) ? 32 : 0) + sr * CCH;
        const float* g = src + base + (size_t)c * (HH * WW) + gh * WW;
        #pragma unroll
        for (int i = 0; i < 2; i++) {
            const int f4 = chunk + 8 * i;        // 0..15
            float4 val = make_float4(0.f, 0.f, 0.f, 0.f);
            if (inb) val = *(const float4*)(g + f4 * 4);
            *(__half2*)(tile + hrow + 2 + f4 * 4)     = __floats2half2_rn(val.x, val.y);
            *(__half2*)(tile + hrow + 2 + f4 * 4 + 2) = __floats2half2_rn(val.z, val.w);
        }
        if (chunk == 0) *(__half2*)(tile + hrow)      = __float2half2_rn(0.f);
        if (chunk == 7) *(__half2*)(tile + hrow + 66) = __float2half2_rn(0.f);
    }
}

__global__ __launch_bounds__(256, 3)
void dilate_attn_kernel(const float* __restrict__ q,
                        const float* __restrict__ k,
                        const float* __restrict__ v,
                        float* __restrict__ out)
{
    extern __shared__ __half smem[];
    __half* kt = smem;                       // k tile
    __half* vt = smem + TILE_HALVES;         // v tile

    const int tid  = threadIdx.x;            // 0..255
    const int lane = tid & 31;
    const int wp   = tid >> 5;               // warp 0..7
    const int pair = wp * 16 + (lane & 15);  // 0..127
    const int row  = pair >> 5;              // 0..3  pixel row in tile
    const int w    = (pair & 31) * 2;        // even pixel column
    const int ch0  = lane & 16;              // 0 or 16: channel half base

    const int h0   = blockIdx.x * TH;
    const int bh   = blockIdx.y;             // 0..47
    const int b    = bh / NH;
    const int head = bh - b * NH;
    const size_t base = ((size_t)b * 384 + (size_t)head * HD) * (HH * WW);

    // ---- q: 16 channels x 2 pixels packed (coalesced LDG.64, issued first) ----
    const int h = h0 + row;
    uint64_t q2[16];
    {
        const uint64_t* qp =
            (const uint64_t*)(q + base + (size_t)ch0 * (HH * WW) + h * WW + w);
        #pragma unroll
        for (int c = 0; c < 16; c++) q2[c] = __ldg(qp + (size_t)c * 2048);
    }

    // ---- stage BOTH tensors as fp16 (one MLP-rich prologue burst) ----
    stage_tensor(k, kt, wp, lane, h0, base);
    stage_tensor(v, vt, wp, lane, h0, base);

    __syncthreads();                         // THE barrier

    // ---- QK: packed partial logits over this thread's 16 channels ----
    const int chbase = ch0 ? HI_OFF : 0;
    uint64_t lg2[9];
    #pragma unroll
    for (int kp = 0; kp < 9; kp++) {
        const int di = kp / 3;
        const int dj = kp - di * 3;
        const __half2* kr =
            (const __half2*)(kt + chbase + (row + 2 * di) * CCH + w + 2 * dj);
        uint64_t a = 0;
        #pragma unroll
        for (int c = 0; c < 16; c++)
            ffma2(a, q2[c], h2_to_f2(kr[c * (PSH / 2)]));
        lg2[kp] = a;
    }

    // ---- combine halves (packed shuffle) + softmax for both pixels ----
    float l0[9], l1[9];
    #pragma unroll
    for (int kp = 0; kp < 9; kp++) {
        const double part = __longlong_as_double((long long)lg2[kp]);
        const double oth  = __shfl_xor_sync(0xffffffffu, part, 16);
        const uint64_t full = fadd2(lg2[kp], (uint64_t)__double_as_longlong(oth));
        unpack2(full, l0[kp], l1[kp]);
        l0[kp] *= SCALE; l1[kp] *= SCALE;    // OOB neighbor: k==0 -> logit 0 (zero-pad)
    }
    float m0 = l0[0], m1 = l1[0];
    #pragma unroll
    for (int kp = 1; kp < 9; kp++) { m0 = fmaxf(m0, l0[kp]); m1 = fmaxf(m1, l1[kp]); }
    float sum0 = 0.f, sum1 = 0.f;
    uint64_t p2[9];
    #pragma unroll
    for (int kp = 0; kp < 9; kp++) {
        const float e0 = __expf(l0[kp] - m0);
        const float e1 = __expf(l1[kp] - m1);
        sum0 += e0; sum1 += e1;
        p2[kp] = pack2(e0, e1);
    }
    const uint64_t inv2 = pack2(__fdividef(1.f, sum0), __fdividef(1.f, sum1));

    // ---- AV: packed weighted sum over this thread's 16 channels ----
    uint64_t acc2[16];
    #pragma unroll
    for (int c = 0; c < 16; c++) acc2[c] = 0;
    #pragma unroll
    for (int kp = 0; kp < 9; kp++) {
        const int di = kp / 3;
        const int dj = kp - di * 3;
        const __half2* vr =
            (const __half2*)(vt + chbase + (row + 2 * di) * CCH + w + 2 * dj);
        #pragma unroll
        for (int c = 0; c < 16; c++)
            ffma2(acc2[c], p2[kp], h2_to_f2(vr[c * (PSH / 2)]));
    }

    // ---- stores: 2 pixels x 64B contiguous each (8 STG.128 total) ----
    const size_t ob = (((size_t)b * HH + h) * WW + w) * 384
                      + (size_t)head * HD + ch0;
    float4* d0 = (float4*)(out + ob);            // pixel w
    float4* d1 = (float4*)(out + ob + 384);      // pixel w+1
    #pragma unroll
    for (int i = 0; i < 4; i++) {
        float x0, y0, x1, y1, x2, y2, x3, y3;
        unpack2(fmul2(acc2[4 * i + 0], inv2), x0, y0);
        unpack2(fmul2(acc2[4 * i + 1], inv2), x1, y1);
        unpack2(fmul2(acc2[4 * i + 2], inv2), x2, y2);
        unpack2(fmul2(acc2[4 * i + 3], inv2), x3, y3);
        d0[i] = make_float4(x0, x1, x2, x3);
        d1[i] = make_float4(y0, y1, y2, y3);
    }
}

extern "C" void kernel_launch(void* const* d_in, const int* in_sizes, int n_in,
                              void* d_out, int out_size)
{
    const float* q = (const float*)d_in[0];
    const float* k = (const float*)d_in[1];
    const float* v = (const float*)d_in[2];
    float* out = (float*)d_out;

    const int smem_bytes = 2 * TILE_HALVES * sizeof(__half);   // 69760
    cudaFuncSetAttribute(dilate_attn_kernel,
                         cudaFuncAttributeMaxDynamicSharedMemorySize, smem_bytes);

    dim3 block(256, 1, 1);
    dim3 grid(HH / TH, 4 * NH, 1);          // (16, 48)
    dilate_attn_kernel<<<grid, block, smem_bytes>>>(q, k, v, out);
}